// round 15
// baseline (speedup 1.0000x reference)
#include <cuda_runtime.h>
#include <cuda_fp16.h>
#include <cstdint>
#include <cstddef>

#define B_BATCH 1024
#define T_STEPS 100
#define N_IN    784
#define N_HID   100
#define N_OUT   10
#define M_TOT   (B_BATCH * T_STEPS)   // 102400

#define NCHP  50          // k16 chunks, padded (chunk 49 = zeros)
#define NCHV  49          // valid chunks (49*16 = 784)
#define NST   25          // stages of 2 chunks

// Scratch
__device__ float g_YT[(size_t)N_HID * M_TOT];   // Y^T [100][102400]
// Packed fp16 A-fragments of W1 (hi/mid), k-permuted, split by column half.
__device__ uint4 g_AH0[NCHP * 4 * 32];
__device__ uint4 g_AM0[NCHP * 4 * 32];
__device__ uint4 g_AH1[NCHP * 3 * 32];
__device__ uint4 g_AM1[NCHP * 3 * 32];

// ---------------- fp16 helpers ----------------
static __device__ __forceinline__ uint32_t packh2(__half a, __half b) {
    __half2 h = __halves2half2(a, b);
    return *reinterpret_cast<uint32_t*>(&h);
}
static __device__ __forceinline__ void split_f16(float x, __half& h, __half& m) {
    h = __float2half_rn(x);
    m = __float2half_rn(x - __half2float(h));
}
static __device__ __forceinline__ void mma_f16(
    float& d0, float& d1, float& d2, float& d3,
    uint32_t a0, uint32_t a1, uint32_t a2, uint32_t a3,
    uint32_t b0, uint32_t b1)
{
    asm volatile(
        "mma.sync.aligned.m16n8k16.row.col.f32.f16.f16.f32 "
        "{%0,%1,%2,%3}, {%4,%5,%6,%7}, {%8,%9}, {%0,%1,%2,%3};\n"
        : "+f"(d0), "+f"(d1), "+f"(d2), "+f"(d3)
        : "r"(a0), "r"(a1), "r"(a2), "r"(a3), "r"(b0), "r"(b1));
}

// ---------------- cp.async helpers ----------------
static __device__ __forceinline__ uint32_t smem_u32(const void* p) {
    uint32_t a;
    asm("{ .reg .u64 t; cvta.to.shared.u64 t, %1; cvt.u32.u64 %0, t; }"
        : "=r"(a) : "l"(p));
    return a;
}
static __device__ __forceinline__ void cp_async16(uint32_t dst, const void* src) {
    asm volatile("cp.async.ca.shared.global [%0], [%1], 16;"
                 :: "r"(dst), "l"(src) : "memory");
}
static __device__ __forceinline__ void cp_commit() {
    asm volatile("cp.async.commit_group;" ::: "memory");
}
static __device__ __forceinline__ void cp_wait1() {
    asm volatile("cp.async.wait_group 1;" ::: "memory");
}
static __device__ __forceinline__ void cp_wait0() {
    asm volatile("cp.async.wait_group 0;" ::: "memory");
}

// ============ Prep: pack W1 into k-permuted fp16 hi/mid A-fragments ========
__global__ __launch_bounds__(256) void prep_a_kernel(const float* __restrict__ W1)
{
    const int gid = blockIdx.x * 256 + threadIdx.x;
    if (gid >= NCHP * 7 * 32) return;
    const int lane = gid & 31;
    const int mt   = (gid >> 5) % 7;
    const int c    = (gid >> 5) / 7;
    const int q = lane >> 2, r = lane & 3;
    const int kb = 16 * c + 4 * r;
    const int n0 = mt * 16 + q;
    const int n1 = n0 + 8;
    const bool kv = (c < NCHV);

    float w0a = 0.f, w0b = 0.f, w0c = 0.f, w0d = 0.f;
    float w1a = 0.f, w1b = 0.f, w1c = 0.f, w1d = 0.f;
    if (kv) {
        if (n0 < N_HID) {
            w0a = W1[(size_t)n0 * N_IN + kb];
            w0b = W1[(size_t)n0 * N_IN + kb + 1];
            w0c = W1[(size_t)n0 * N_IN + kb + 2];
            w0d = W1[(size_t)n0 * N_IN + kb + 3];
        }
        if (n1 < N_HID) {
            w1a = W1[(size_t)n1 * N_IN + kb];
            w1b = W1[(size_t)n1 * N_IN + kb + 1];
            w1c = W1[(size_t)n1 * N_IN + kb + 2];
            w1d = W1[(size_t)n1 * N_IN + kb + 3];
        }
    }

    __half h0a, m0a, h0b, m0b, h0c, m0c, h0d, m0d;
    __half h1a, m1a, h1b, m1b, h1c, m1c, h1d, m1d;
    split_f16(w0a, h0a, m0a); split_f16(w0b, h0b, m0b);
    split_f16(w0c, h0c, m0c); split_f16(w0d, h0d, m0d);
    split_f16(w1a, h1a, m1a); split_f16(w1b, h1b, m1b);
    split_f16(w1c, h1c, m1c); split_f16(w1d, h1d, m1d);

    uint4 H, M;
    H.x = packh2(h0a, h0b);
    H.y = packh2(h1a, h1b);
    H.z = packh2(h0c, h0d);
    H.w = packh2(h1c, h1d);
    M.x = packh2(m0a, m0b);
    M.y = packh2(m1a, m1b);
    M.z = packh2(m0c, m0d);
    M.w = packh2(m1c, m1d);

    if (mt < 4) {
        const int idx = (c * 4 + mt) * 32 + lane;
        g_AH0[idx] = H;
        g_AM0[idx] = M;
    } else {
        const int idx = (c * 3 + (mt - 4)) * 32 + lane;
        g_AH1[idx] = H;
        g_AM1[idx] = M;
    }
}

// ============ GEMM1: YT[n][m] = sum_k W1[n,k] X[m,k] (fp16x3) ============
// grid (800, 2): x = 128-row m-block, y = column half. 256 thr, 3 CTA/SM.
template <int NMTY, int MTBASE>
static __device__ __forceinline__ void gemm_half(
    const float* __restrict__ X,
    const uint4* __restrict__ Ah, const uint4* __restrict__ Am,
    uint4* As)
{
    constexpr int CHPC = NMTY * 32;
    const int tid  = threadIdx.x;
    const int warp = tid >> 5;
    const int lane = tid & 31;
    const int q = lane >> 2, r = lane & 3;
    const int m0w = blockIdx.x * 128 + warp * 16;

    float acc[NMTY][2][4];
#pragma unroll
    for (int mt = 0; mt < NMTY; ++mt)
#pragma unroll
        for (int nt = 0; nt < 2; ++nt)
#pragma unroll
            for (int i = 0; i < 4; ++i) acc[mt][nt][i] = 0.f;

    const float4* xr[2];
#pragma unroll
    for (int nt = 0; nt < 2; ++nt)
        xr[nt] = reinterpret_cast<const float4*>(X)
               + (size_t)(m0w + nt * 8 + q) * (N_IN / 4) + r;

    const uint32_t as_base = smem_u32(As);

    auto stage = [&](int st, int b) {
        const uint32_t dst = as_base + (uint32_t)(b * 4 * CHPC) * 16u;
        const uint4* srcH = Ah + (size_t)(2 * st) * CHPC;
        const uint4* srcM = Am + (size_t)(2 * st) * CHPC;
#pragma unroll
        for (int i = tid; i < 2 * CHPC; i += 256) {
            cp_async16(dst + (uint32_t)i * 16u,                srcH + i);
            cp_async16(dst + (uint32_t)(2 * CHPC + i) * 16u,   srcM + i);
        }
        cp_commit();
    };

    stage(0, 0);
    float4 V[2], Vn[2];
#pragma unroll
    for (int nt = 0; nt < 2; ++nt) V[nt] = xr[nt][0];

    for (int st = 0; st < NST; ++st) {
        const int b = st & 1;
        if (st + 1 < NST) { stage(st + 1, b ^ 1); cp_wait1(); }
        else              { cp_wait0(); }
        __syncthreads();

        const uint4* Ab = As + b * 4 * CHPC;

#pragma unroll
        for (int i = 0; i < 2; ++i) {
            const int ch = 2 * st + i;
            const int cn = ch + 1;
#pragma unroll
            for (int nt = 0; nt < 2; ++nt)
                Vn[nt] = (cn < NCHV) ? xr[nt][(size_t)cn * 4]
                                     : make_float4(0.f, 0.f, 0.f, 0.f);

            if (ch < NCHV) {
                uint32_t bh[2][2], bm[2][2];
#pragma unroll
                for (int nt = 0; nt < 2; ++nt) {
                    __half h0, m0, h1, m1, h2, m2, h3, m3;
                    split_f16(V[nt].x, h0, m0);
                    split_f16(V[nt].y, h1, m1);
                    split_f16(V[nt].z, h2, m2);
                    split_f16(V[nt].w, h3, m3);
                    bh[nt][0] = packh2(h0, h1);
                    bh[nt][1] = packh2(h2, h3);
                    bm[nt][0] = packh2(m0, m1);
                    bm[nt][1] = packh2(m2, m3);
                }

#pragma unroll
                for (int mt = 0; mt < NMTY; ++mt) {
                    const uint4 AH = Ab[i * CHPC + mt * 32 + lane];
                    const uint4 AM = Ab[2 * CHPC + i * CHPC + mt * 32 + lane];
#pragma unroll
                    for (int nt = 0; nt < 2; ++nt)
                        mma_f16(acc[mt][nt][0], acc[mt][nt][1],
                                acc[mt][nt][2], acc[mt][nt][3],
                                AH.x, AH.y, AH.z, AH.w, bh[nt][0], bh[nt][1]);
#pragma unroll
                    for (int nt = 0; nt < 2; ++nt)
                        mma_f16(acc[mt][nt][0], acc[mt][nt][1],
                                acc[mt][nt][2], acc[mt][nt][3],
                                AH.x, AH.y, AH.z, AH.w, bm[nt][0], bm[nt][1]);
#pragma unroll
                    for (int nt = 0; nt < 2; ++nt)
                        mma_f16(acc[mt][nt][0], acc[mt][nt][1],
                                acc[mt][nt][2], acc[mt][nt][3],
                                AM.x, AM.y, AM.z, AM.w, bh[nt][0], bh[nt][1]);
                }
            }

#pragma unroll
            for (int nt = 0; nt < 2; ++nt) V[nt] = Vn[nt];
        }
        __syncthreads();
    }

    // epilogue -> YT[n][m]
#pragma unroll
    for (int mt = 0; mt < NMTY; ++mt) {
        const int n0 = (MTBASE + mt) * 16 + q;
#pragma unroll
        for (int nt = 0; nt < 2; ++nt) {
            const int m = m0w + nt * 8 + 2 * r;
            if (n0 < N_HID)
                *reinterpret_cast<float2*>(g_YT + (size_t)n0 * M_TOT + m) =
                    make_float2(acc[mt][nt][0], acc[mt][nt][1]);
            if (n0 + 8 < N_HID)
                *reinterpret_cast<float2*>(g_YT + (size_t)(n0 + 8) * M_TOT + m) =
                    make_float2(acc[mt][nt][2], acc[mt][nt][3]);
        }
    }
}

__global__ __launch_bounds__(256, 3) void gemm1_mma_kernel(const float* __restrict__ X)
{
    // max half (NMTY=4): 2 buffers x 2 parts x 2 chunks x 128 uint4 = 16 KB
    __shared__ uint4 As[2 * 4 * (4 * 32)];
    if (blockIdx.y == 0)
        gemm_half<4, 0>(X, g_AH0, g_AM0, As);
    else
        gemm_half<3, 4>(X, g_AH1, g_AM1, As);
}

// ============ Fused SNN: scan1 + gemm2 + scan2, one block per batch b ======
// Y tile staged in smem (coalesced loads); w2s/h2s alias the dead ysm region.
#define YROW 101   // padded row stride (conflict-free scalar LDS)

__global__ __launch_bounds__(128) void snn_fused_kernel(
    const float* __restrict__ w_syn1, const float* __restrict__ b1,
    const float* __restrict__ w_syn2, const float* __restrict__ W2,
    const float* __restrict__ b2, float* __restrict__ out)
{
    __shared__ float    ysm[N_HID * YROW];   // 40.4 KB; aliased after phase 1
    __shared__ uint32_t spw[N_HID * 4];      // spike bits [h][word]

    const int b   = blockIdx.x;
    const int tid = threadIdx.x;

    // ---- phase 0: stage Y tile (coalesced float4 from YT rows) ----
    {
        const float* base = g_YT + (size_t)b * T_STEPS;
        for (int idx = tid; idx < N_HID * 25; idx += 128) {
            const int row = idx / 25;
            const int c4  = idx % 25;
            const float4 v = *reinterpret_cast<const float4*>(
                base + (size_t)row * M_TOT + c4 * 4);
            float* dst = ysm + row * YROW + c4 * 4;
            dst[0] = v.x; dst[1] = v.y; dst[2] = v.z; dst[3] = v.w;
        }
    }
    __syncthreads();

    // ---- phase 1: layer-1 scan, thread = h ----
    if (tid < N_HID) {
        const int h = tid;
        const float inv1 = 1.f / (1.f + expf(-w_syn1[0]));
        const float bh = b1[h];
        const float* yp = ysm + h * YROW;

        float hs = 0.f, v = 0.f;
        uint32_t w[4] = {0u, 0u, 0u, 0u};
#pragma unroll 4
        for (int t = 0; t < T_STEPS; ++t) {
            hs = (hs - hs * inv1) + yp[t];          // SynapseFilter 1
            const float h1 = hs + bh;
            v = v + (h1 - v) * 0.5f;                // LIF decay (tau=2)
            if (v >= 1.0f) {
                w[t >> 5] |= (1u << (t & 31));
                v = 0.f;                            // hard reset
            }
        }
#pragma unroll
        for (int k = 0; k < 4; ++k) spw[h * 4 + k] = w[k];
    }
    __syncthreads();

    // ---- alias: w2s and h2s live in the (now dead) ysm region ----
    float* w2s = ysm;            // [h*10+o], 1000 floats
    float* h2s = ysm + 1024;     // [o*100+t], 1000 floats

    for (int i = tid; i < N_HID * N_OUT; i += 128) {
        const int o = i / N_HID, h = i % N_HID;
        w2s[h * N_OUT + o] = W2[i];
    }
    __syncthreads();

    // ---- phase 2: H2[o][t] = sum_h bit(h,t) * W2[o,h], thread = t ----
    if (tid < T_STEPS) {
        const int t = tid;
        const int wrd = t >> 5, bit = t & 31;
        float acc[N_OUT];
#pragma unroll
        for (int o = 0; o < N_OUT; ++o) acc[o] = 0.f;
#pragma unroll 4
        for (int h = 0; h < N_HID; ++h) {
            const uint32_t word = spw[h * 4 + wrd];
            const float v = (float)((word >> bit) & 1u);
#pragma unroll
            for (int o = 0; o < N_OUT; ++o)
                acc[o] = fmaf(v, w2s[h * N_OUT + o], acc[o]);
        }
#pragma unroll
        for (int o = 0; o < N_OUT; ++o) h2s[o * T_STEPS + t] = acc[o];
    }
    __syncthreads();

    // ---- phase 3: layer-2 scan, thread = o ----
    if (tid < N_OUT) {
        const int o = tid;
        const float inv2 = 1.f / (1.f + expf(-w_syn2[0]));
        const float bo = b2[o];
        const float* hp = h2s + o * T_STEPS;

        float hs = 0.f, v = 0.f;
#pragma unroll 4
        for (int t = 0; t < T_STEPS; ++t) {
            const float p = hp[t];
            hs = (hs - hs * inv2) + p;   // SynapseFilter 2
            const float h2 = hs + bo;
            v = v + (h2 - v) * 0.5f;     // LIF 2 (soft reset @thr 0 -> no-op)
        }
        out[b * N_OUT + o] = v;
    }
}

// ---------------- entry ----------------
extern "C" void kernel_launch(void* const* d_in, const int* in_sizes, int n_in,
                              void* d_out, int out_size) {
    const float* x   = (const float*)d_in[0];  // [1024, 100, 784]
    const float* w1s = (const float*)d_in[1];
    const float* W1  = (const float*)d_in[2];  // [100, 784]
    const float* b1  = (const float*)d_in[3];
    const float* w2s = (const float*)d_in[4];
    const float* W2  = (const float*)d_in[5];  // [10, 100]
    const float* b2  = (const float*)d_in[6];
    float* out = (float*)d_out;                // [1024, 10]

    prep_a_kernel<<<(NCHP * 7 * 32 + 255) / 256, 256>>>(W1);
    gemm1_mma_kernel<<<dim3(M_TOT / 128, 2), 256>>>(x);
    snn_fused_kernel<<<B_BATCH, 128>>>(w1s, b1, w2s, W2, b2, out);
}

// round 16
// speedup vs baseline: 1.0438x; 1.0438x over previous
#include <cuda_runtime.h>
#include <cuda_fp16.h>
#include <cstdint>
#include <cstddef>

#define B_BATCH 1024
#define T_STEPS 100
#define N_IN    784
#define N_HID   100
#define N_OUT   10
#define M_TOT   (B_BATCH * T_STEPS)   // 102400

#define NCHP  50          // k16 chunks, padded (chunk 49 = zeros)
#define NCHV  49          // valid chunks (49*16 = 784)
#define NST   25          // stages of 2 chunks

// Scratch
__device__ float g_YT[(size_t)N_HID * M_TOT];   // Y^T [100][102400]
// Packed fp16 A-fragments of W1 (hi/mid), k-permuted, split by column half.
__device__ uint4 g_AH0[NCHP * 4 * 32];
__device__ uint4 g_AM0[NCHP * 4 * 32];
__device__ uint4 g_AH1[NCHP * 3 * 32];
__device__ uint4 g_AM1[NCHP * 3 * 32];

// ---------------- fp16 helpers ----------------
static __device__ __forceinline__ uint32_t packh2(__half a, __half b) {
    __half2 h = __halves2half2(a, b);
    return *reinterpret_cast<uint32_t*>(&h);
}
static __device__ __forceinline__ void split_f16(float x, __half& h, __half& m) {
    h = __float2half_rn(x);
    m = __float2half_rn(x - __half2float(h));
}
static __device__ __forceinline__ void mma_f16(
    float& d0, float& d1, float& d2, float& d3,
    uint32_t a0, uint32_t a1, uint32_t a2, uint32_t a3,
    uint32_t b0, uint32_t b1)
{
    asm volatile(
        "mma.sync.aligned.m16n8k16.row.col.f32.f16.f16.f32 "
        "{%0,%1,%2,%3}, {%4,%5,%6,%7}, {%8,%9}, {%0,%1,%2,%3};\n"
        : "+f"(d0), "+f"(d1), "+f"(d2), "+f"(d3)
        : "r"(a0), "r"(a1), "r"(a2), "r"(a3), "r"(b0), "r"(b1));
}

// ---------------- cp.async helpers ----------------
static __device__ __forceinline__ uint32_t smem_u32(const void* p) {
    uint32_t a;
    asm("{ .reg .u64 t; cvta.to.shared.u64 t, %1; cvt.u32.u64 %0, t; }"
        : "=r"(a) : "l"(p));
    return a;
}
static __device__ __forceinline__ void cp_async16(uint32_t dst, const void* src) {
    asm volatile("cp.async.ca.shared.global [%0], [%1], 16;"
                 :: "r"(dst), "l"(src) : "memory");
}
static __device__ __forceinline__ void cp_commit() {
    asm volatile("cp.async.commit_group;" ::: "memory");
}
static __device__ __forceinline__ void cp_wait1() {
    asm volatile("cp.async.wait_group 1;" ::: "memory");
}
static __device__ __forceinline__ void cp_wait0() {
    asm volatile("cp.async.wait_group 0;" ::: "memory");
}

// ============ Prep: pack W1 into k-permuted fp16 hi/mid A-fragments ========
__global__ __launch_bounds__(256) void prep_a_kernel(const float* __restrict__ W1)
{
    const int gid = blockIdx.x * 256 + threadIdx.x;
    if (gid >= NCHP * 7 * 32) return;
    const int lane = gid & 31;
    const int mt   = (gid >> 5) % 7;
    const int c    = (gid >> 5) / 7;
    const int q = lane >> 2, r = lane & 3;
    const int kb = 16 * c + 4 * r;
    const int n0 = mt * 16 + q;
    const int n1 = n0 + 8;
    const bool kv = (c < NCHV);

    float w0a = 0.f, w0b = 0.f, w0c = 0.f, w0d = 0.f;
    float w1a = 0.f, w1b = 0.f, w1c = 0.f, w1d = 0.f;
    if (kv) {
        if (n0 < N_HID) {
            w0a = W1[(size_t)n0 * N_IN + kb];
            w0b = W1[(size_t)n0 * N_IN + kb + 1];
            w0c = W1[(size_t)n0 * N_IN + kb + 2];
            w0d = W1[(size_t)n0 * N_IN + kb + 3];
        }
        if (n1 < N_HID) {
            w1a = W1[(size_t)n1 * N_IN + kb];
            w1b = W1[(size_t)n1 * N_IN + kb + 1];
            w1c = W1[(size_t)n1 * N_IN + kb + 2];
            w1d = W1[(size_t)n1 * N_IN + kb + 3];
        }
    }

    __half h0a, m0a, h0b, m0b, h0c, m0c, h0d, m0d;
    __half h1a, m1a, h1b, m1b, h1c, m1c, h1d, m1d;
    split_f16(w0a, h0a, m0a); split_f16(w0b, h0b, m0b);
    split_f16(w0c, h0c, m0c); split_f16(w0d, h0d, m0d);
    split_f16(w1a, h1a, m1a); split_f16(w1b, h1b, m1b);
    split_f16(w1c, h1c, m1c); split_f16(w1d, h1d, m1d);

    uint4 H, M;
    H.x = packh2(h0a, h0b);
    H.y = packh2(h1a, h1b);
    H.z = packh2(h0c, h0d);
    H.w = packh2(h1c, h1d);
    M.x = packh2(m0a, m0b);
    M.y = packh2(m1a, m1b);
    M.z = packh2(m0c, m0d);
    M.w = packh2(m1c, m1d);

    if (mt < 4) {
        const int idx = (c * 4 + mt) * 32 + lane;
        g_AH0[idx] = H;
        g_AM0[idx] = M;
    } else {
        const int idx = (c * 3 + (mt - 4)) * 32 + lane;
        g_AH1[idx] = H;
        g_AM1[idx] = M;
    }
}

// ============ GEMM1: YT[n][m] = sum_k W1[n,k] X[m,k] (fp16x3) ============
// grid (800, 2): x = 128-row m-block, y = column half. 256 thr, 3 CTA/SM.
// EXACTLY the R13 structure: pad chunk computed unconditionally (zeros),
// NO branch inside the mma body.
template <int NMTY, int MTBASE>
static __device__ __forceinline__ void gemm_half(
    const float* __restrict__ X,
    const uint4* __restrict__ Ah, const uint4* __restrict__ Am,
    uint4* As)
{
    constexpr int CHPC = NMTY * 32;       // uint4 per chunk per part
    const int tid  = threadIdx.x;
    const int warp = tid >> 5;
    const int lane = tid & 31;
    const int q = lane >> 2, r = lane & 3;
    const int m0w = blockIdx.x * 128 + warp * 16;

    float acc[NMTY][2][4];
#pragma unroll
    for (int mt = 0; mt < NMTY; ++mt)
#pragma unroll
        for (int nt = 0; nt < 2; ++nt)
#pragma unroll
            for (int i = 0; i < 4; ++i) acc[mt][nt][i] = 0.f;

    const float4* xr[2];
#pragma unroll
    for (int nt = 0; nt < 2; ++nt)
        xr[nt] = reinterpret_cast<const float4*>(X)
               + (size_t)(m0w + nt * 8 + q) * (N_IN / 4) + r;

    const uint32_t as_base = smem_u32(As);

    auto stage = [&](int st, int b) {
        const uint32_t dst = as_base + (uint32_t)(b * 4 * CHPC) * 16u;
        const uint4* srcH = Ah + (size_t)(2 * st) * CHPC;
        const uint4* srcM = Am + (size_t)(2 * st) * CHPC;
#pragma unroll
        for (int i = tid; i < 2 * CHPC; i += 256) {
            cp_async16(dst + (uint32_t)i * 16u,                srcH + i);
            cp_async16(dst + (uint32_t)(2 * CHPC + i) * 16u,   srcM + i);
        }
        cp_commit();
    };

    stage(0, 0);
    float4 V[2], Vn[2];
#pragma unroll
    for (int nt = 0; nt < 2; ++nt) V[nt] = xr[nt][0];

    for (int st = 0; st < NST; ++st) {
        const int b = st & 1;
        if (st + 1 < NST) { stage(st + 1, b ^ 1); cp_wait1(); }
        else              { cp_wait0(); }
        __syncthreads();

        const uint4* Ab = As + b * 4 * CHPC;

#pragma unroll
        for (int i = 0; i < 2; ++i) {
            const int ch = 2 * st + i;
            // prefetch X for next chunk
            const int cn = ch + 1;
#pragma unroll
            for (int nt = 0; nt < 2; ++nt)
                Vn[nt] = (cn < NCHV) ? xr[nt][(size_t)cn * 4]
                                     : make_float4(0.f, 0.f, 0.f, 0.f);

            // B fragments: split X into fp16 hi/mid
            uint32_t bh[2][2], bm[2][2];
#pragma unroll
            for (int nt = 0; nt < 2; ++nt) {
                __half h0, m0, h1, m1, h2, m2, h3, m3;
                split_f16(V[nt].x, h0, m0);
                split_f16(V[nt].y, h1, m1);
                split_f16(V[nt].z, h2, m2);
                split_f16(V[nt].w, h3, m3);
                bh[nt][0] = packh2(h0, h1);
                bh[nt][1] = packh2(h2, h3);
                bm[nt][0] = packh2(m0, m1);
                bm[nt][1] = packh2(m2, m3);
            }

#pragma unroll
            for (int mt = 0; mt < NMTY; ++mt) {
                const uint4 AH = Ab[i * CHPC + mt * 32 + lane];
                const uint4 AM = Ab[2 * CHPC + i * CHPC + mt * 32 + lane];
                // pass 1: Ah * Bh
#pragma unroll
                for (int nt = 0; nt < 2; ++nt)
                    mma_f16(acc[mt][nt][0], acc[mt][nt][1],
                            acc[mt][nt][2], acc[mt][nt][3],
                            AH.x, AH.y, AH.z, AH.w, bh[nt][0], bh[nt][1]);
                // pass 2: Ah * Bm
#pragma unroll
                for (int nt = 0; nt < 2; ++nt)
                    mma_f16(acc[mt][nt][0], acc[mt][nt][1],
                            acc[mt][nt][2], acc[mt][nt][3],
                            AH.x, AH.y, AH.z, AH.w, bm[nt][0], bm[nt][1]);
                // pass 3: Am * Bh
#pragma unroll
                for (int nt = 0; nt < 2; ++nt)
                    mma_f16(acc[mt][nt][0], acc[mt][nt][1],
                            acc[mt][nt][2], acc[mt][nt][3],
                            AM.x, AM.y, AM.z, AM.w, bh[nt][0], bh[nt][1]);
            }

#pragma unroll
            for (int nt = 0; nt < 2; ++nt) V[nt] = Vn[nt];
        }
        __syncthreads();
    }

    // epilogue -> YT[n][m]
#pragma unroll
    for (int mt = 0; mt < NMTY; ++mt) {
        const int n0 = (MTBASE + mt) * 16 + q;
#pragma unroll
        for (int nt = 0; nt < 2; ++nt) {
            const int m = m0w + nt * 8 + 2 * r;
            if (n0 < N_HID)
                *reinterpret_cast<float2*>(g_YT + (size_t)n0 * M_TOT + m) =
                    make_float2(acc[mt][nt][0], acc[mt][nt][1]);
            if (n0 + 8 < N_HID)
                *reinterpret_cast<float2*>(g_YT + (size_t)(n0 + 8) * M_TOT + m) =
                    make_float2(acc[mt][nt][2], acc[mt][nt][3]);
        }
    }
}

__global__ __launch_bounds__(256, 3) void gemm1_mma_kernel(const float* __restrict__ X)
{
    // max half (NMTY=4): 2 buffers x 2 parts x 2 chunks x 128 uint4 = 16 KB
    __shared__ uint4 As[2 * 4 * (4 * 32)];
    if (blockIdx.y == 0)
        gemm_half<4, 0>(X, g_AH0, g_AM0, As);
    else
        gemm_half<3, 4>(X, g_AH1, g_AM1, As);
}

// ============ Fused SNN: scan1 + gemm2 + scan2, one block per batch b ======
// Y tile staged in smem (coalesced loads); w2s/h2s alias the dead ysm region.
#define YROW 101   // padded row stride (conflict-free scalar LDS)

__global__ __launch_bounds__(128) void snn_fused_kernel(
    const float* __restrict__ w_syn1, const float* __restrict__ b1,
    const float* __restrict__ w_syn2, const float* __restrict__ W2,
    const float* __restrict__ b2, float* __restrict__ out)
{
    __shared__ float    ysm[N_HID * YROW];   // 40.4 KB; aliased after phase 1
    __shared__ uint32_t spw[N_HID * 4];      // spike bits [h][word]

    const int b   = blockIdx.x;
    const int tid = threadIdx.x;

    // ---- phase 0: stage Y tile (coalesced float4 from YT rows) ----
    {
        const float* base = g_YT + (size_t)b * T_STEPS;
        for (int idx = tid; idx < N_HID * 25; idx += 128) {
            const int row = idx / 25;
            const int c4  = idx % 25;
            const float4 v = *reinterpret_cast<const float4*>(
                base + (size_t)row * M_TOT + c4 * 4);
            float* dst = ysm + row * YROW + c4 * 4;
            dst[0] = v.x; dst[1] = v.y; dst[2] = v.z; dst[3] = v.w;
        }
    }
    __syncthreads();

    // ---- phase 1: layer-1 scan, thread = h ----
    if (tid < N_HID) {
        const int h = tid;
        const float inv1 = 1.f / (1.f + expf(-w_syn1[0]));
        const float bh = b1[h];
        const float* yp = ysm + h * YROW;

        float hs = 0.f, v = 0.f;
        uint32_t w[4] = {0u, 0u, 0u, 0u};
#pragma unroll 4
        for (int t = 0; t < T_STEPS; ++t) {
            hs = (hs - hs * inv1) + yp[t];          // SynapseFilter 1
            const float h1 = hs + bh;
            v = v + (h1 - v) * 0.5f;                // LIF decay (tau=2)
            if (v >= 1.0f) {
                w[t >> 5] |= (1u << (t & 31));
                v = 0.f;                            // hard reset
            }
        }
#pragma unroll
        for (int k = 0; k < 4; ++k) spw[h * 4 + k] = w[k];
    }
    __syncthreads();

    // ---- alias: w2s and h2s live in the (now dead) ysm region ----
    float* w2s = ysm;            // [h*10+o], 1000 floats
    float* h2s = ysm + 1024;     // [o*100+t], 1000 floats

    for (int i = tid; i < N_HID * N_OUT; i += 128) {
        const int o = i / N_HID, h = i % N_HID;
        w2s[h * N_OUT + o] = W2[i];
    }
    __syncthreads();

    // ---- phase 2: H2[o][t] = sum_h bit(h,t) * W2[o,h], thread = t ----
    if (tid < T_STEPS) {
        const int t = tid;
        const int wrd = t >> 5, bit = t & 31;
        float acc[N_OUT];
#pragma unroll
        for (int o = 0; o < N_OUT; ++o) acc[o] = 0.f;
#pragma unroll 4
        for (int h = 0; h < N_HID; ++h) {
            const uint32_t word = spw[h * 4 + wrd];
            const float v = (float)((word >> bit) & 1u);
#pragma unroll
            for (int o = 0; o < N_OUT; ++o)
                acc[o] = fmaf(v, w2s[h * N_OUT + o], acc[o]);
        }
#pragma unroll
        for (int o = 0; o < N_OUT; ++o) h2s[o * T_STEPS + t] = acc[o];
    }
    __syncthreads();

    // ---- phase 3: layer-2 scan, thread = o ----
    if (tid < N_OUT) {
        const int o = tid;
        const float inv2 = 1.f / (1.f + expf(-w_syn2[0]));
        const float bo = b2[o];
        const float* hp = h2s + o * T_STEPS;

        float hs = 0.f, v = 0.f;
#pragma unroll 4
        for (int t = 0; t < T_STEPS; ++t) {
            const float p = hp[t];
            hs = (hs - hs * inv2) + p;   // SynapseFilter 2
            const float h2 = hs + bo;
            v = v + (h2 - v) * 0.5f;     // LIF 2 (soft reset @thr 0 -> no-op)
        }
        out[b * N_OUT + o] = v;
    }
}

// ---------------- entry ----------------
extern "C" void kernel_launch(void* const* d_in, const int* in_sizes, int n_in,
                              void* d_out, int out_size) {
    const float* x   = (const float*)d_in[0];  // [1024, 100, 784]
    const float* w1s = (const float*)d_in[1];
    const float* W1  = (const float*)d_in[2];  // [100, 784]
    const float* b1  = (const float*)d_in[3];
    const float* w2s = (const float*)d_in[4];
    const float* W2  = (const float*)d_in[5];  // [10, 100]
    const float* b2  = (const float*)d_in[6];
    float* out = (float*)d_out;                // [1024, 10]

    prep_a_kernel<<<(NCHP * 7 * 32 + 255) / 256, 256>>>(W1);
    gemm1_mma_kernel<<<dim3(M_TOT / 128, 2), 256>>>(x);
    snn_fused_kernel<<<B_BATCH, 128>>>(w1s, b1, w2s, W2, b2, out);
}

// round 17
// speedup vs baseline: 1.1483x; 1.1001x over previous
#include <cuda_runtime.h>
#include <cuda_fp16.h>
#include <cstdint>
#include <cstddef>

#define B_BATCH 1024
#define T_STEPS 100
#define N_IN    784
#define N_HID   100
#define N_OUT   10
#define M_TOT   (B_BATCH * T_STEPS)   // 102400

#define NCHP  50          // k16 chunks, padded (chunk 49 = zeros)
#define NCHV  49          // valid chunks (49*16 = 784)
#define NST   25          // stages of 2 chunks

// Scratch: Y in NATURAL [m][h] layout (m = b*100+t)
__device__ float g_Y[(size_t)M_TOT * N_HID];
// Packed fp16 A-fragments of W1 (hi/mid), k-permuted, split by column half.
__device__ uint4 g_AH0[NCHP * 4 * 32];
__device__ uint4 g_AM0[NCHP * 4 * 32];
__device__ uint4 g_AH1[NCHP * 3 * 32];
__device__ uint4 g_AM1[NCHP * 3 * 32];

// ---------------- fp16 helpers ----------------
static __device__ __forceinline__ uint32_t packh2(__half a, __half b) {
    __half2 h = __halves2half2(a, b);
    return *reinterpret_cast<uint32_t*>(&h);
}
static __device__ __forceinline__ void split_f16(float x, __half& h, __half& m) {
    h = __float2half_rn(x);
    m = __float2half_rn(x - __half2float(h));
}
static __device__ __forceinline__ void mma_f16(
    float& d0, float& d1, float& d2, float& d3,
    uint32_t a0, uint32_t a1, uint32_t a2, uint32_t a3,
    uint32_t b0, uint32_t b1)
{
    asm volatile(
        "mma.sync.aligned.m16n8k16.row.col.f32.f16.f16.f32 "
        "{%0,%1,%2,%3}, {%4,%5,%6,%7}, {%8,%9}, {%0,%1,%2,%3};\n"
        : "+f"(d0), "+f"(d1), "+f"(d2), "+f"(d3)
        : "r"(a0), "r"(a1), "r"(a2), "r"(a3), "r"(b0), "r"(b1));
}

// ---------------- cp.async helpers ----------------
static __device__ __forceinline__ uint32_t smem_u32(const void* p) {
    uint32_t a;
    asm("{ .reg .u64 t; cvta.to.shared.u64 t, %1; cvt.u32.u64 %0, t; }"
        : "=r"(a) : "l"(p));
    return a;
}
static __device__ __forceinline__ void cp_async16(uint32_t dst, const void* src) {
    asm volatile("cp.async.ca.shared.global [%0], [%1], 16;"
                 :: "r"(dst), "l"(src) : "memory");
}
static __device__ __forceinline__ void cp_commit() {
    asm volatile("cp.async.commit_group;" ::: "memory");
}
static __device__ __forceinline__ void cp_wait1() {
    asm volatile("cp.async.wait_group 1;" ::: "memory");
}
static __device__ __forceinline__ void cp_wait0() {
    asm volatile("cp.async.wait_group 0;" ::: "memory");
}

// ============ Prep: pack W1 into k-permuted fp16 hi/mid A-fragments ========
__global__ __launch_bounds__(256) void prep_a_kernel(const float* __restrict__ W1)
{
    const int gid = blockIdx.x * 256 + threadIdx.x;
    if (gid >= NCHP * 7 * 32) return;
    const int lane = gid & 31;
    const int mt   = (gid >> 5) % 7;
    const int c    = (gid >> 5) / 7;
    const int q = lane >> 2, r = lane & 3;
    const int kb = 16 * c + 4 * r;
    const int n0 = mt * 16 + q;
    const int n1 = n0 + 8;
    const bool kv = (c < NCHV);

    float w0a = 0.f, w0b = 0.f, w0c = 0.f, w0d = 0.f;
    float w1a = 0.f, w1b = 0.f, w1c = 0.f, w1d = 0.f;
    if (kv) {
        if (n0 < N_HID) {
            w0a = W1[(size_t)n0 * N_IN + kb];
            w0b = W1[(size_t)n0 * N_IN + kb + 1];
            w0c = W1[(size_t)n0 * N_IN + kb + 2];
            w0d = W1[(size_t)n0 * N_IN + kb + 3];
        }
        if (n1 < N_HID) {
            w1a = W1[(size_t)n1 * N_IN + kb];
            w1b = W1[(size_t)n1 * N_IN + kb + 1];
            w1c = W1[(size_t)n1 * N_IN + kb + 2];
            w1d = W1[(size_t)n1 * N_IN + kb + 3];
        }
    }

    __half h0a, m0a, h0b, m0b, h0c, m0c, h0d, m0d;
    __half h1a, m1a, h1b, m1b, h1c, m1c, h1d, m1d;
    split_f16(w0a, h0a, m0a); split_f16(w0b, h0b, m0b);
    split_f16(w0c, h0c, m0c); split_f16(w0d, h0d, m0d);
    split_f16(w1a, h1a, m1a); split_f16(w1b, h1b, m1b);
    split_f16(w1c, h1c, m1c); split_f16(w1d, h1d, m1d);

    uint4 H, M;
    H.x = packh2(h0a, h0b);
    H.y = packh2(h1a, h1b);
    H.z = packh2(h0c, h0d);
    H.w = packh2(h1c, h1d);
    M.x = packh2(m0a, m0b);
    M.y = packh2(m1a, m1b);
    M.z = packh2(m0c, m0d);
    M.w = packh2(m1c, m1d);

    if (mt < 4) {
        const int idx = (c * 4 + mt) * 32 + lane;
        g_AH0[idx] = H;
        g_AM0[idx] = M;
    } else {
        const int idx = (c * 3 + (mt - 4)) * 32 + lane;
        g_AH1[idx] = H;
        g_AM1[idx] = M;
    }
}

// ============ GEMM1: Y[m][n] = sum_k X[m,k] W1[n,k] (fp16x3) ============
// grid (800, 2): x = 128-row m-block, y = column half. 256 thr, 3 CTA/SM.
// R13 structure exactly (pad chunk computed unconditionally, no mma-body branch).
template <int NMTY, int MTBASE>
static __device__ __forceinline__ void gemm_half(
    const float* __restrict__ X,
    const uint4* __restrict__ Ah, const uint4* __restrict__ Am,
    uint4* As)
{
    constexpr int CHPC = NMTY * 32;       // uint4 per chunk per part
    const int tid  = threadIdx.x;
    const int warp = tid >> 5;
    const int lane = tid & 31;
    const int q = lane >> 2, r = lane & 3;
    const int m0w = blockIdx.x * 128 + warp * 16;

    float acc[NMTY][2][4];
#pragma unroll
    for (int mt = 0; mt < NMTY; ++mt)
#pragma unroll
        for (int nt = 0; nt < 2; ++nt)
#pragma unroll
            for (int i = 0; i < 4; ++i) acc[mt][nt][i] = 0.f;

    const float4* xr[2];
#pragma unroll
    for (int nt = 0; nt < 2; ++nt)
        xr[nt] = reinterpret_cast<const float4*>(X)
               + (size_t)(m0w + nt * 8 + q) * (N_IN / 4) + r;

    const uint32_t as_base = smem_u32(As);

    auto stage = [&](int st, int b) {
        const uint32_t dst = as_base + (uint32_t)(b * 4 * CHPC) * 16u;
        const uint4* srcH = Ah + (size_t)(2 * st) * CHPC;
        const uint4* srcM = Am + (size_t)(2 * st) * CHPC;
#pragma unroll
        for (int i = tid; i < 2 * CHPC; i += 256) {
            cp_async16(dst + (uint32_t)i * 16u,                srcH + i);
            cp_async16(dst + (uint32_t)(2 * CHPC + i) * 16u,   srcM + i);
        }
        cp_commit();
    };

    stage(0, 0);
    float4 V[2], Vn[2];
#pragma unroll
    for (int nt = 0; nt < 2; ++nt) V[nt] = xr[nt][0];

    for (int st = 0; st < NST; ++st) {
        const int b = st & 1;
        if (st + 1 < NST) { stage(st + 1, b ^ 1); cp_wait1(); }
        else              { cp_wait0(); }
        __syncthreads();

        const uint4* Ab = As + b * 4 * CHPC;

#pragma unroll
        for (int i = 0; i < 2; ++i) {
            const int ch = 2 * st + i;
            const int cn = ch + 1;
#pragma unroll
            for (int nt = 0; nt < 2; ++nt)
                Vn[nt] = (cn < NCHV) ? xr[nt][(size_t)cn * 4]
                                     : make_float4(0.f, 0.f, 0.f, 0.f);

            uint32_t bh[2][2], bm[2][2];
#pragma unroll
            for (int nt = 0; nt < 2; ++nt) {
                __half h0, m0, h1, m1, h2, m2, h3, m3;
                split_f16(V[nt].x, h0, m0);
                split_f16(V[nt].y, h1, m1);
                split_f16(V[nt].z, h2, m2);
                split_f16(V[nt].w, h3, m3);
                bh[nt][0] = packh2(h0, h1);
                bh[nt][1] = packh2(h2, h3);
                bm[nt][0] = packh2(m0, m1);
                bm[nt][1] = packh2(m2, m3);
            }

#pragma unroll
            for (int mt = 0; mt < NMTY; ++mt) {
                const uint4 AH = Ab[i * CHPC + mt * 32 + lane];
                const uint4 AM = Ab[2 * CHPC + i * CHPC + mt * 32 + lane];
#pragma unroll
                for (int nt = 0; nt < 2; ++nt)
                    mma_f16(acc[mt][nt][0], acc[mt][nt][1],
                            acc[mt][nt][2], acc[mt][nt][3],
                            AH.x, AH.y, AH.z, AH.w, bh[nt][0], bh[nt][1]);
#pragma unroll
                for (int nt = 0; nt < 2; ++nt)
                    mma_f16(acc[mt][nt][0], acc[mt][nt][1],
                            acc[mt][nt][2], acc[mt][nt][3],
                            AH.x, AH.y, AH.z, AH.w, bm[nt][0], bm[nt][1]);
#pragma unroll
                for (int nt = 0; nt < 2; ++nt)
                    mma_f16(acc[mt][nt][0], acc[mt][nt][1],
                            acc[mt][nt][2], acc[mt][nt][3],
                            AM.x, AM.y, AM.z, AM.w, bh[nt][0], bh[nt][1]);
            }

#pragma unroll
            for (int nt = 0; nt < 2; ++nt) V[nt] = Vn[nt];
        }
        __syncthreads();
    }

    // epilogue -> Y[m][n] (natural layout; scalar stores, 4 lines/inst)
#pragma unroll
    for (int mt = 0; mt < NMTY; ++mt) {
        const int n0 = (MTBASE + mt) * 16 + q;
        const int n1 = n0 + 8;
#pragma unroll
        for (int nt = 0; nt < 2; ++nt) {
            const int m = m0w + nt * 8 + 2 * r;
            if (n0 < N_HID) {
                g_Y[(size_t)m * N_HID + n0]       = acc[mt][nt][0];
                g_Y[(size_t)(m + 1) * N_HID + n0] = acc[mt][nt][1];
            }
            if (n1 < N_HID) {
                g_Y[(size_t)m * N_HID + n1]       = acc[mt][nt][2];
                g_Y[(size_t)(m + 1) * N_HID + n1] = acc[mt][nt][3];
            }
        }
    }
}

__global__ __launch_bounds__(256, 3) void gemm1_mma_kernel(const float* __restrict__ X)
{
    __shared__ uint4 As[2 * 4 * (4 * 32)];   // 16 KB (max half)
    if (blockIdx.y == 0)
        gemm_half<4, 0>(X, g_AH0, g_AM0, As);
    else
        gemm_half<3, 4>(X, g_AH1, g_AM1, As);
}

// ============ Fused SNN: scan1 + gemm2 + scan2, one block per batch b ======
// Y natural layout -> phase-1 loads are lane-coalesced (1 line / load inst).
__global__ __launch_bounds__(128) void snn_fused_kernel(
    const float* __restrict__ w_syn1, const float* __restrict__ b1,
    const float* __restrict__ w_syn2, const float* __restrict__ W2,
    const float* __restrict__ b2, float* __restrict__ out)
{
    __shared__ float    w2s[N_HID * N_OUT];    // [h*10+o]
    __shared__ uint32_t spw[N_HID * 4];        // spike bits [h][word]
    __shared__ float    h2s[N_OUT * T_STEPS];  // [o*100+t]

    const int b   = blockIdx.x;
    const int tid = threadIdx.x;

    for (int i = tid; i < N_HID * N_OUT; i += 128) {
        const int o = i / N_HID, h = i % N_HID;
        w2s[h * N_OUT + o] = W2[i];
    }

    // ---- phase 1: layer-1 scan, thread = h (coalesced loads across lanes) ----
    if (tid < N_HID) {
        const int h = tid;
        const float inv1 = 1.f / (1.f + expf(-w_syn1[0]));
        const float bh = b1[h];
        const float* yb = g_Y + (size_t)b * T_STEPS * N_HID + h;

        float hs = 0.f, v = 0.f;
        uint32_t w[4] = {0u, 0u, 0u, 0u};
#pragma unroll 4
        for (int t = 0; t < T_STEPS; ++t) {
            hs = (hs - hs * inv1) + yb[(size_t)t * N_HID];   // SynapseFilter 1
            const float h1 = hs + bh;
            v = v + (h1 - v) * 0.5f;                // LIF decay (tau=2)
            if (v >= 1.0f) {
                w[t >> 5] |= (1u << (t & 31));
                v = 0.f;                            // hard reset
            }
        }
#pragma unroll
        for (int k = 0; k < 4; ++k) spw[h * 4 + k] = w[k];
    }
    __syncthreads();

    // ---- phase 2: H2[o][t] = sum_h bit(h,t) * W2[o,h], thread = t ----
    if (tid < T_STEPS) {
        const int t = tid;
        const int wrd = t >> 5, bit = t & 31;
        float acc[N_OUT];
#pragma unroll
        for (int o = 0; o < N_OUT; ++o) acc[o] = 0.f;
#pragma unroll 4
        for (int h = 0; h < N_HID; ++h) {
            const uint32_t word = spw[h * 4 + wrd];
            const float v = (float)((word >> bit) & 1u);
#pragma unroll
            for (int o = 0; o < N_OUT; ++o)
                acc[o] = fmaf(v, w2s[h * N_OUT + o], acc[o]);
        }
#pragma unroll
        for (int o = 0; o < N_OUT; ++o) h2s[o * T_STEPS + t] = acc[o];
    }
    __syncthreads();

    // ---- phase 3: layer-2 scan, thread = o ----
    if (tid < N_OUT) {
        const int o = tid;
        const float inv2 = 1.f / (1.f + expf(-w_syn2[0]));
        const float bo = b2[o];
        const float* hp = h2s + o * T_STEPS;

        float hs = 0.f, v = 0.f;
#pragma unroll 4
        for (int t = 0; t < T_STEPS; ++t) {
            const float p = hp[t];
            hs = (hs - hs * inv2) + p;   // SynapseFilter 2
            const float h2 = hs + bo;
            v = v + (h2 - v) * 0.5f;     // LIF 2 (soft reset @thr 0 -> no-op)
        }
        out[b * N_OUT + o] = v;
    }
}

// ---------------- entry ----------------
extern "C" void kernel_launch(void* const* d_in, const int* in_sizes, int n_in,
                              void* d_out, int out_size) {
    const float* x   = (const float*)d_in[0];  // [1024, 100, 784]
    const float* w1s = (const float*)d_in[1];
    const float* W1  = (const float*)d_in[2];  // [100, 784]
    const float* b1  = (const float*)d_in[3];
    const float* w2s = (const float*)d_in[4];
    const float* W2  = (const float*)d_in[5];  // [10, 100]
    const float* b2  = (const float*)d_in[6];
    float* out = (float*)d_out;                // [1024, 10]

    prep_a_kernel<<<(NCHP * 7 * 32 + 255) / 256, 256>>>(W1);
    gemm1_mma_kernel<<<dim3(M_TOT / 128, 2), 256>>>(x);
    snn_fused_kernel<<<B_BATCH, 128>>>(w1s, b1, w2s, W2, b2, out);
}